// round 8
// baseline (speedup 1.0000x reference)
#include <cuda_runtime.h>
#include <cstdint>
#include <math_constants.h>

#define N_NODES 32768
#define N_PER   512
#define BGRAPH  64
#define E_EDGES 524288
#define C_IN    32
#define HDIM    128
#define KTLS    8
#define A_DIM   8
#define NSLOTS  512
#define ECAP    1024

// ---------------- scratch (device globals; no allocs allowed) ----------------
__device__ float g_as[N_NODES];
__device__ float g_ad[N_NODES];
__device__ int   g_cur[NSLOTS];          // zero-init at load; k_agg re-zeros
__device__ int   g_srcs[NSLOTS * ECAP];
__device__ __align__(16) float g_feats[BGRAPH * 1024];
__device__ __align__(16) float g_p1[8  * BGRAPH * 2048];   // gemm1 partials, 4 MB
__device__ __align__(16) float g_p2[16 * BGRAPH * 512];    // gemm2 partials, 2 MB

union F4U { float4 v; unsigned long long u[2]; float f[4]; };

// ---------------- fused att + edge-filter kernel ----------------
// blocks [0,128): node attention scalars; [128,2178): edge filter
__global__ void k_pre(const float* __restrict__ x, const float* __restrict__ W,
                      const float* __restrict__ att_src, const float* __restrict__ att_dst,
                      const int* __restrict__ ei, const int* __restrict__ tls) {
    __shared__ float ws[C_IN], wd[C_IN];
    __shared__ int tl[KTLS];
    int t = threadIdx.x;
    if (blockIdx.x < 128) {
        if (t < 64) {
            int c = t & 31;
            const float* av = (t < 32) ? att_src : att_dst;
            float s = 0.f;
#pragma unroll 8
            for (int d = 0; d < HDIM; d++) s = fmaf(W[c * HDIM + d], av[d], s);
            if (t < 32) ws[c] = s; else wd[c] = s;
        }
        __syncthreads();
        int n = blockIdx.x * 256 + t;
        const float4* xr = (const float4*)(x + n * C_IN);
        float s1 = 0.f, s2 = 0.f;
#pragma unroll
        for (int q = 0; q < 8; q++) {
            float4 v = xr[q];
            s1 = fmaf(v.x, ws[q*4+0], s1); s2 = fmaf(v.x, wd[q*4+0], s2);
            s1 = fmaf(v.y, ws[q*4+1], s1); s2 = fmaf(v.y, wd[q*4+1], s2);
            s1 = fmaf(v.z, ws[q*4+2], s1); s2 = fmaf(v.z, wd[q*4+2], s2);
            s1 = fmaf(v.w, ws[q*4+3], s1); s2 = fmaf(v.w, wd[q*4+3], s2);
        }
        g_as[n] = s1;
        g_ad[n] = s2;
    } else {
        if (t < KTLS) tl[t] = tls[t];
        __syncthreads();
        long i = (long)(blockIdx.x - 128) * 256 + t;     // < 524800 exactly
        if (i < E_EDGES) {
            int d = ei[E_EDGES + i];
            int loc = d & (N_PER - 1);
            int b = d >> 9;
            int s = -1;
#pragma unroll
            for (int k = 0; k < KTLS; k++) {
                if (tl[k] == loc) {
                    if (s < 0) s = ei[i];
                    int slot = b * KTLS + k;
                    int p = atomicAdd(&g_cur[slot], 1);
                    if (p < ECAP) g_srcs[slot * ECAP + p] = s;
                }
            }
        } else {                                          // self loops
            int slot = (int)(i - E_EDGES);
            int b = slot >> 3, k = slot & 7;
            int n = b * N_PER + tl[k];
            int p = atomicAdd(&g_cur[slot], 1);
            if (p < ECAP) g_srcs[slot * ECAP + p] = n;
        }
    }
}

// ---------------- per-target softmax + aggregation -> feats ----------------
__global__ void k_agg(const float* __restrict__ x, const float* __restrict__ W,
                      const int* __restrict__ tls, const float* __restrict__ b_gat) {
    __shared__ float Ws[C_IN * HDIM];
    __shared__ float e_s[ECAP];
    __shared__ int   s_s[ECAP];
    __shared__ float racc[4][HDIM];
    __shared__ float rden[4];
    __shared__ float red4[4];
    __shared__ float m_sh;

    int slot = blockIdx.x;
    int b = slot >> 3, k = slot & 7;
    int t = threadIdx.x;
    int w = t >> 5, l = t & 31;
    int n = b * N_PER + tls[k];
    float ad_n = g_ad[n];
    int deg = g_cur[slot];
    if (deg > ECAP) deg = ECAP;

    {
        const float4* Wg = (const float4*)W;
        float4* Wl = (float4*)Ws;
        for (int u = t; u < C_IN * HDIM / 4; u += 128) Wl[u] = Wg[u];
    }

    float lmax = -CUDART_INF_F;
    for (int j = t; j < deg; j += 128) {
        int s = g_srcs[slot * ECAP + j];
        float e = g_as[s] + ad_n;
        e = e > 0.f ? e : 0.2f * e;
        e_s[j] = e;
        s_s[j] = s;
        lmax = fmaxf(lmax, e);
    }
#pragma unroll
    for (int off = 16; off; off >>= 1)
        lmax = fmaxf(lmax, __shfl_xor_sync(0xFFFFFFFFu, lmax, off));
    if (l == 0) red4[w] = lmax;
    __syncthreads();
    if (t == 0) m_sh = fmaxf(fmaxf(red4[0], red4[1]), fmaxf(red4[2], red4[3]));
    __syncthreads();
    float m = m_sh;

    float4 acc = make_float4(0.f, 0.f, 0.f, 0.f);
    float den = 0.f;
    const float4* Ws4 = (const float4*)Ws;
    for (int j = w; j < deg; j += 4) {
        int s = s_s[j];
        float ex = __expf(e_s[j] - m);
        den += ex;
        float xv = x[s * C_IN + l];
        float4 h = make_float4(0.f, 0.f, 0.f, 0.f);
#pragma unroll
        for (int c = 0; c < C_IN; c++) {
            float xc = __shfl_sync(0xFFFFFFFFu, xv, c);
            float4 wv = Ws4[c * 32 + l];
            h.x = fmaf(xc, wv.x, h.x);
            h.y = fmaf(xc, wv.y, h.y);
            h.z = fmaf(xc, wv.z, h.z);
            h.w = fmaf(xc, wv.w, h.w);
        }
        acc.x = fmaf(ex, h.x, acc.x);
        acc.y = fmaf(ex, h.y, acc.y);
        acc.z = fmaf(ex, h.z, acc.z);
        acc.w = fmaf(ex, h.w, acc.w);
    }
    *((float4*)&racc[w][4 * l]) = acc;
    if (l == 0) rden[w] = den;
    __syncthreads();

    float tot = racc[0][t] + racc[1][t] + racc[2][t] + racc[3][t];
    float dtot = rden[0] + rden[1] + rden[2] + rden[3];
    float v = tot / (dtot + 1e-16f) + b_gat[t];
    v = v > 0.f ? v : expm1f(v);
    g_feats[b * (KTLS * HDIM) + k * HDIM + t] = v;
    if (t == 0) g_cur[slot] = 0;       // reset cursor for next graph replay
}

// ---------------- gemm1: feats[64,1024] @ {vW1,aW1}[1024,1024] -> p1 partials -
// grid (32, 8): x = head*16 + jtile, y = k-chunk (KC=128). 256 threads.
// Tile 64x64, thread tile 4x4 (2 f32x2 row-pairs x 4 cols). Dynamic smem 68 KB.
#define G1_KC 128
#define G1_STR 68
#define G1_SMEM (2 * G1_KC * G1_STR * 4)

__global__ void __launch_bounds__(256) k_gemm1(
        const float* __restrict__ vW1, const float* __restrict__ aW1) {
    extern __shared__ float sm[];
    float* As = sm;                 // [128][68] transposed As[k][row]
    float* Ws = sm + G1_KC * G1_STR;

    int z  = blockIdx.x >> 4;
    int j0 = (blockIdx.x & 15) * 64;
    int c  = blockIdx.y;
    int k0 = c * G1_KC;
    int tid = threadIdx.x;
    const float* Wg = z ? aW1 : vW1;

    // stage A: 64 rows x 128 k (2048 float4, 8 per thread)
    for (int e = tid; e < 2048; e += 256) {
        int r = e >> 5, kq = e & 31;
        float4 v = *(const float4*)(g_feats + r * 1024 + k0 + kq * 4);
        As[(kq * 4 + 0) * G1_STR + r] = v.x;
        As[(kq * 4 + 1) * G1_STR + r] = v.y;
        As[(kq * 4 + 2) * G1_STR + r] = v.z;
        As[(kq * 4 + 3) * G1_STR + r] = v.w;
    }
    // stage W: 128 k x 64 cols
    for (int e = tid; e < 2048; e += 256) {
        int kk = e >> 4, jq = e & 15;
        float4 v = *(const float4*)(Wg + (long)(k0 + kk) * 1024 + j0 + jq * 4);
        *(float4*)&Ws[kk * G1_STR + jq * 4] = v;
    }
    __syncthreads();

    int r0 = (tid >> 4) * 4;      // 16 row-groups of 4
    int jb = (tid & 15) * 4;      // 16 col-groups of 4

    unsigned long long acc[2][4];
#pragma unroll
    for (int i = 0; i < 2; i++)
#pragma unroll
        for (int j = 0; j < 4; j++) acc[i][j] = 0ull;

#pragma unroll 8
    for (int kk = 0; kk < G1_KC; kk++) {
        F4U a, w;
        a.v = *(float4*)&As[kk * G1_STR + r0];
        w.v = *(float4*)&Ws[kk * G1_STR + jb];
#pragma unroll
        for (int j = 0; j < 4; j++) {
            unsigned long long wd;
            asm("mov.b64 %0, {%1, %1};" : "=l"(wd) : "f"(w.f[j]));
            asm("fma.rn.f32x2 %0, %1, %2, %0;" : "+l"(acc[0][j]) : "l"(a.u[0]), "l"(wd));
            asm("fma.rn.f32x2 %0, %1, %2, %0;" : "+l"(acc[1][j]) : "l"(a.u[1]), "l"(wd));
        }
    }

    // write partials: p1[c][row][z*1024 + j0 + jb ...]
    float* base = g_p1 + (long)c * 64 * 2048 + z * 1024 + j0 + jb;
#pragma unroll
    for (int rp = 0; rp < 2; rp++) {
        float lo[4], hi[4];
#pragma unroll
        for (int j = 0; j < 4; j++)
            asm("mov.b64 {%0, %1}, %2;" : "=f"(lo[j]), "=f"(hi[j]) : "l"(acc[rp][j]));
        *(float4*)(base + (long)(r0 + 2 * rp)     * 2048) = make_float4(lo[0], lo[1], lo[2], lo[3]);
        *(float4*)(base + (long)(r0 + 2 * rp + 1) * 2048) = make_float4(hi[0], hi[1], hi[2], hi[3]);
    }
}

// ---------------- gemm2: relu(sum p1 + b1) @ {vW2,aW2}[1024,256] -> p2 --------
// grid (16, 16): x = head*8 + jtile(32 cols), y = k-chunk (KC=64). 128 threads.
// Tile 64x32, thread tile 8x2 (4 f32x2 row-pairs x 2 cols).
#define G2_KC 64
#define G2_ASTR 68
#define G2_WSTR 36

__global__ void __launch_bounds__(128) k_gemm2(
        const float* __restrict__ vb1, const float* __restrict__ ab1,
        const float* __restrict__ vW2, const float* __restrict__ aW2) {
    __shared__ float As[G2_KC * G2_ASTR];
    __shared__ float Ws[G2_KC * G2_WSTR];

    int z  = blockIdx.x >> 3;
    int j0 = (blockIdx.x & 7) * 32;
    int c  = blockIdx.y;
    int k0 = c * G2_KC;               // within head-K 1024
    int tid = threadIdx.x;
    const float* Wg = z ? aW2 : vW2;
    const float* bin = z ? ab1 : vb1;

    // stage W: 64 k x 32 cols (512 float4, 4 per thread)
    for (int e = tid; e < 512; e += 128) {
        int kk = e >> 3, jq = e & 7;
        float4 v = *(const float4*)(Wg + (long)(k0 + kk) * 256 + j0 + jq * 4);
        *(float4*)&Ws[kk * G2_WSTR + jq * 4] = v;
    }
    // stage A: 64 rows x 64 k, summing 8 p1 chunks + bias + relu (1024 f4, 8/thread)
    {
        const float* pbase = g_p1 + z * 1024 + k0;
        for (int e = tid; e < 1024; e += 128) {
            int r = e >> 4, kq = e & 15;
            const float* src = pbase + (long)r * 2048 + kq * 4;
            float4 s0 = *(const float4*)(src);
            float4 s1 = *(const float4*)(src + 1 * 64 * 2048);
            float4 s2 = *(const float4*)(src + 2 * 64 * 2048);
            float4 s3 = *(const float4*)(src + 3 * 64 * 2048);
            float4 s4 = *(const float4*)(src + 4 * 64 * 2048);
            float4 s5 = *(const float4*)(src + 5 * 64 * 2048);
            float4 s6 = *(const float4*)(src + 6 * 64 * 2048);
            float4 s7 = *(const float4*)(src + 7 * 64 * 2048);
            float4 bb = *(const float4*)(bin + k0 + kq * 4);
            float vx = fmaxf(((s0.x + s1.x) + (s2.x + s3.x)) + ((s4.x + s5.x) + (s6.x + s7.x)) + bb.x, 0.f);
            float vy = fmaxf(((s0.y + s1.y) + (s2.y + s3.y)) + ((s4.y + s5.y) + (s6.y + s7.y)) + bb.y, 0.f);
            float vz = fmaxf(((s0.z + s1.z) + (s2.z + s3.z)) + ((s4.z + s5.z) + (s6.z + s7.z)) + bb.z, 0.f);
            float vw = fmaxf(((s0.w + s1.w) + (s2.w + s3.w)) + ((s4.w + s5.w) + (s6.w + s7.w)) + bb.w, 0.f);
            As[(kq * 4 + 0) * G2_ASTR + r] = vx;
            As[(kq * 4 + 1) * G2_ASTR + r] = vy;
            As[(kq * 4 + 2) * G2_ASTR + r] = vz;
            As[(kq * 4 + 3) * G2_ASTR + r] = vw;
        }
    }
    __syncthreads();

    int r0 = (tid >> 4) * 8;      // 8 row-groups of 8
    int jb = (tid & 15) * 2;      // 16 col-groups of 2

    unsigned long long acc[4][2];
#pragma unroll
    for (int i = 0; i < 4; i++) { acc[i][0] = 0ull; acc[i][1] = 0ull; }

#pragma unroll 8
    for (int kk = 0; kk < G2_KC; kk++) {
        F4U a0, a1;
        a0.v = *(float4*)&As[kk * G2_ASTR + r0];
        a1.v = *(float4*)&As[kk * G2_ASTR + r0 + 4];
        float2 w = *(float2*)&Ws[kk * G2_WSTR + jb];
        unsigned long long ap[4] = {a0.u[0], a0.u[1], a1.u[0], a1.u[1]};
#pragma unroll
        for (int j = 0; j < 2; j++) {
            unsigned long long wd;
            float wf = (j == 0) ? w.x : w.y;
            asm("mov.b64 %0, {%1, %1};" : "=l"(wd) : "f"(wf));
            asm("fma.rn.f32x2 %0, %1, %2, %0;" : "+l"(acc[0][j]) : "l"(ap[0]), "l"(wd));
            asm("fma.rn.f32x2 %0, %1, %2, %0;" : "+l"(acc[1][j]) : "l"(ap[1]), "l"(wd));
            asm("fma.rn.f32x2 %0, %1, %2, %0;" : "+l"(acc[2][j]) : "l"(ap[2]), "l"(wd));
            asm("fma.rn.f32x2 %0, %1, %2, %0;" : "+l"(acc[3][j]) : "l"(ap[3]), "l"(wd));
        }
    }

    // write partials: p2[c][row][z*256 + j0 + jb ...]
    float* base = g_p2 + (long)c * 64 * 512 + z * 256 + j0 + jb;
#pragma unroll
    for (int rp = 0; rp < 4; rp++) {
        float lo0, hi0, lo1, hi1;
        asm("mov.b64 {%0, %1}, %2;" : "=f"(lo0), "=f"(hi0) : "l"(acc[rp][0]));
        asm("mov.b64 {%0, %1}, %2;" : "=f"(lo1), "=f"(hi1) : "l"(acc[rp][1]));
        *(float2*)(base + (long)(r0 + 2 * rp)     * 512) = make_float2(lo0, lo1);
        *(float2*)(base + (long)(r0 + 2 * rp + 1) * 512) = make_float2(hi0, hi1);
    }
}

// ---------------- per-graph tail: p2-sum + L3 + L4 + dueling combine ----------
__global__ void __launch_bounds__(256) k_tail(
        const float* __restrict__ vb2, const float* __restrict__ ab2,
        const float* __restrict__ vW3, const float* __restrict__ vb3,
        const float* __restrict__ aW3, const float* __restrict__ ab3,
        const float* __restrict__ vW4, const float* __restrict__ vb4,
        const float* __restrict__ aW4, const float* __restrict__ ab4,
        float* __restrict__ out) {
    __shared__ float h2s[512];
    __shared__ float part[128][2];
    __shared__ float h3s[128];
    __shared__ float res[9];
    int b = blockIdx.x;
    int t = threadIdx.x;

    // assemble h2: sum 16 p2 chunks + bias + relu (2 cols per thread)
    for (int e = t; e < 512; e += 256) {
        const float* src = g_p2 + b * 512 + e;
        float s = 0.f;
#pragma unroll
        for (int cc = 0; cc < 16; cc++) s += src[cc * 64 * 512];
        s += (e < 256) ? vb2[e] : ab2[e - 256];
        h2s[e] = fmaxf(s, 0.f);
    }
    __syncthreads();

    // L3: 128 outputs, K=256 split into two halves across thread pairs
    {
        int o = t & 127;          // output index
        int half = t >> 7;        // K half
        int head = o >> 6, j = o & 63;
        const float* W3 = head ? aW3 : vW3;
        const float* hh = h2s + head * 256 + half * 128;
        const float* wp = W3 + (half * 128) * 64 + j;
        float s = 0.f;
#pragma unroll 8
        for (int kq = 0; kq < 128; kq++) s = fmaf(hh[kq], wp[kq * 64], s);
        part[o][half] = s;
    }
    __syncthreads();
    if (t < 128) {
        int head = t >> 6, j = t & 63;
        float s = part[t][0] + part[t][1] + (head ? ab3[j] : vb3[j]);
        h3s[t] = fmaxf(s, 0.f);
    }
    __syncthreads();

    // L4: 9 dots of length 64
    if (t < 9) {
        const float* hrow = &h3s[(t == 0) ? 0 : 64];
        float s = (t == 0) ? vb4[0] : ab4[t - 1];
        if (t == 0) {
#pragma unroll 8
            for (int c = 0; c < 64; c++) s = fmaf(hrow[c], vW4[c], s);
        } else {
#pragma unroll 8
            for (int c = 0; c < 64; c++) s = fmaf(hrow[c], aW4[c * A_DIM + (t - 1)], s);
        }
        res[t] = s;
    }
    __syncthreads();
    if (t < 8) {
        float m = 0.f;
#pragma unroll
        for (int q = 1; q < 9; q++) m += res[q];
        m *= 0.125f;
        out[b * A_DIM + t] = res[0] + res[1 + t] - m;
    }
}

// ---------------- launch ----------------
extern "C" void kernel_launch(void* const* d_in, const int* in_sizes, int n_in,
                              void* d_out, int out_size) {
    const float* x       = (const float*)d_in[0];
    const int*   ei      = (const int*)  d_in[1];
    const int*   tls     = (const int*)  d_in[2];
    const float* W       = (const float*)d_in[3];
    const float* att_src = (const float*)d_in[4];
    const float* att_dst = (const float*)d_in[5];
    const float* b_gat   = (const float*)d_in[6];
    const float* vW1 = (const float*)d_in[7];  const float* vb1 = (const float*)d_in[8];
    const float* vW2 = (const float*)d_in[9];  const float* vb2 = (const float*)d_in[10];
    const float* vW3 = (const float*)d_in[11]; const float* vb3 = (const float*)d_in[12];
    const float* vW4 = (const float*)d_in[13]; const float* vb4 = (const float*)d_in[14];
    const float* aW1 = (const float*)d_in[15]; const float* ab1 = (const float*)d_in[16];
    const float* aW2 = (const float*)d_in[17]; const float* ab2 = (const float*)d_in[18];
    const float* aW3 = (const float*)d_in[19]; const float* ab3 = (const float*)d_in[20];
    const float* aW4 = (const float*)d_in[21]; const float* ab4 = (const float*)d_in[22];

    cudaFuncSetAttribute(k_gemm1, cudaFuncAttributeMaxDynamicSharedMemorySize, G1_SMEM);

    k_pre<<<2178, 256>>>(x, W, att_src, att_dst, ei, tls);
    k_agg<<<NSLOTS, 128>>>(x, W, tls, b_gat);
    k_gemm1<<<dim3(32, 8), 256, G1_SMEM>>>(vW1, aW1);
    k_gemm2<<<dim3(16, 16), 128>>>(vb1, ab1, vW2, aW2);
    k_tail<<<BGRAPH, 256>>>(vb2, ab2, vW3, vb3, aW3, ab3,
                            vW4, vb4, aW4, ab4, (float*)d_out);
}